// round 10
// baseline (speedup 1.0000x reference)
#include <cuda_runtime.h>
#include <cstdint>
#include <math.h>

#define F_DIM 2048
#define K_DIM 128
#define BM    128
#define BK    64
#define NT    (F_DIM / BK)     // 32 k-tiles of 64

// ---- smem layout: sub-tile = R8-proven 32-f tile ----
#define A_BLK_F4   33
#define A_SUB_F4   (32 * A_BLK_F4)            // 1056 f4 = 16896 B
#define B_BLK_F2   132
#define B_SUB_F2   (16 * B_BLK_F2)            // 2112 f2 = 16896 B
#define SM_A_BYTES (4 * A_SUB_F4 * 16)        // 2 bufs x 2 subs = 67584
#define SM_B_OFF   SM_A_BYTES
#define SM_B_BYTES (4 * B_SUB_F2 * 8)         // 67584
#define SM_PS_OFF  (SM_B_OFF + SM_B_BYTES)    // float[128][4]
#define SM_RLIN_OFF (SM_PS_OFF + 2048)
#define SM_RT_OFF   (SM_RLIN_OFF + 512)
#define SMEM_BYTES  (SM_RT_OFF + 512)         // 138240

__device__ float  g_wcvt[F_DIM * K_DIM];   // tf32-rounded W, [f][n]
__device__ float2 g_ws[F_DIM];             // {wlin[f], exact sum_k W[f,k]^2}

__device__ __forceinline__ float to_tf32(float x) {
    uint32_t u;
    asm("cvt.rna.tf32.f32 %0, %1;" : "=r"(u) : "f"(x));
    return __uint_as_float(u);
}
__device__ __forceinline__ void mma_tf32(float* d, uint32_t a0, uint32_t a1,
                                         uint32_t a2, uint32_t a3,
                                         uint32_t b0, uint32_t b1) {
    asm volatile(
        "mma.sync.aligned.m16n8k8.row.col.f32.tf32.tf32.f32 "
        "{%0,%1,%2,%3}, {%4,%5,%6,%7}, {%8,%9}, {%0,%1,%2,%3};"
        : "+f"(d[0]), "+f"(d[1]), "+f"(d[2]), "+f"(d[3])
        : "r"(a0), "r"(a1), "r"(a2), "r"(a3), "r"(b0), "r"(b1));
}

// ---------------- fused prologue ----------------
__global__ void prep_kernel(const float* __restrict__ kern,
                            const float* __restrict__ wlin) {
    const int gw = (blockIdx.x * blockDim.x + threadIdx.x) >> 5;  // 0..511
    const int lane = threadIdx.x & 31;
#pragma unroll
    for (int rr = 0; rr < 4; ++rr) {
        const int f = gw * 4 + rr;
        float4 v = *reinterpret_cast<const float4*>(kern + (size_t)f * K_DIM + lane * 4);
        float s = v.x * v.x + v.y * v.y + v.z * v.z + v.w * v.w;
#pragma unroll
        for (int off = 16; off >= 1; off >>= 1)
            s += __shfl_xor_sync(0xffffffffu, s, off);
        float4 c = make_float4(to_tf32(v.x), to_tf32(v.y), to_tf32(v.z), to_tf32(v.w));
        *reinterpret_cast<float4*>(g_wcvt + (size_t)f * K_DIM + lane * 4) = c;
        if (lane == 0) g_ws[f] = make_float2(wlin[f], s);
    }
}

// ---------------- main kernel: 512 threads, 16 warps ----------------
__global__ __launch_bounds__(512, 1) void fm_mma_kernel(
    const float* __restrict__ X, const float* __restrict__ blin,
    float* __restrict__ out) {
    extern __shared__ char smem[];
    float4* Af  = reinterpret_cast<float4*>(smem);
    float2* Bf  = reinterpret_cast<float2*>(smem + SM_B_OFF);
    float*  pS  = reinterpret_cast<float*>(smem + SM_PS_OFF);
    float*  rowLin = reinterpret_cast<float*>(smem + SM_RLIN_OFF);
    float*  rowT   = reinterpret_cast<float*>(smem + SM_RT_OFF);

    const int tid  = threadIdx.x;
    const int lane = tid & 31;
    const int wid  = tid >> 5;
    const int wm   = wid >> 2;              // 0..3 (32-row slice)
    const int wn   = wid & 3;               // 0..3 (32-col slice)
    const int blockRow = blockIdx.x * BM;
    const bool isA = (tid < 256);

    // A loader mapping (tid 0..255)
    const int rid  = tid >> 2;
    const int cseg = tid & 3;
    const int rlow = (rid & 7) | ((rid >> 3) << 4);
    const int wm2i = rid >> 3;
    // B loader mapping (tid 256..511)
    const int t2    = tid & 255;
    const int ksl   = t2 >> 6;
    const int nseg2 = (t2 >> 2) & 15;
    const int c0l   = t2 & 3;

    const float* xLo = X + (size_t)(blockRow + rlow) * F_DIM + cseg * 8;
    const float* xHi = xLo + 8 * F_DIM;
    const float* wLo = g_wcvt + (size_t)(ksl * 8 + c0l) * K_DIM + nseg2 * 8;
    const float* wHi = wLo + 4 * K_DIM;
    const float4* wsP = reinterpret_cast<const float4*>(g_ws) + cseg * 4;

    float linLo = 0.f, linHi = 0.f, tLo = 0.f, tHi = 0.f;
    float acc[2][4][4];
#pragma unroll
    for (int i = 0; i < 2; ++i)
#pragma unroll
        for (int j = 0; j < 4; ++j)
#pragma unroll
            for (int e = 0; e < 4; ++e) acc[i][j][e] = 0.f;

    float4 st[4];   // contiguous staged half-tile

    auto ldg_half = [&](int f0) {
        if (isA) {
            st[0] = *reinterpret_cast<const float4*>(xLo + f0);
            st[1] = *reinterpret_cast<const float4*>(xLo + f0 + 4);
            st[2] = *reinterpret_cast<const float4*>(xHi + f0);
            st[3] = *reinterpret_cast<const float4*>(xHi + f0 + 4);
            const float4* wp = wsP + f0 / 2;
            const float* lo = reinterpret_cast<const float*>(&st[0]);
            const float* hi = reinterpret_cast<const float*>(&st[2]);
#pragma unroll
            for (int u = 0; u < 4; ++u) {
                float4 g = __ldg(wp + u);
                float a0 = lo[2 * u], a1 = lo[2 * u + 1];
                float b0 = hi[2 * u], b1 = hi[2 * u + 1];
                linLo += a0 * g.x + a1 * g.z;  tLo += a0 * a0 * g.y + a1 * a1 * g.w;
                linHi += b0 * g.x + b1 * g.z;  tHi += b0 * b0 * g.y + b1 * b1 * g.w;
            }
        } else {
            st[0] = *reinterpret_cast<const float4*>(wLo + (size_t)f0 * K_DIM);
            st[1] = *reinterpret_cast<const float4*>(wLo + (size_t)f0 * K_DIM + 4);
            st[2] = *reinterpret_cast<const float4*>(wHi + (size_t)f0 * K_DIM);
            st[3] = *reinterpret_cast<const float4*>(wHi + (size_t)f0 * K_DIM + 4);
        }
    };
    auto sts_half = [&](int buf, int s) {
        if (isA) {
            float4* ad = Af + (buf * 2 + s) * A_SUB_F4 + (wm2i * 4 + cseg) * A_BLK_F4;
            const float* lo = reinterpret_cast<const float*>(&st[0]);
            const float* hi = reinterpret_cast<const float*>(&st[2]);
#pragma unroll
            for (int e = 0; e < 4; ++e) {
                int fl = (rlow & 7) * 4 + e;
                ad[fl] = make_float4(lo[e], hi[e], lo[e + 4], hi[e + 4]);
            }
        } else {
            float4* bd = reinterpret_cast<float4*>(Bf + (buf * 2 + s) * B_SUB_F2) +
                         (ksl * 4 + c0l) * (B_BLK_F2 / 2) + nseg2 * 4;
            const float* bl = reinterpret_cast<const float*>(&st[0]);
            const float* bh = reinterpret_cast<const float*>(&st[2]);
#pragma unroll
            for (int e = 0; e < 4; ++e)
                bd[e] = make_float4(bl[2 * e], bh[2 * e], bl[2 * e + 1], bh[2 * e + 1]);
        }
    };
    auto compute_sub = [&](int buf, int s) {
        const float4* ab = Af + (buf * 2 + s) * A_SUB_F4 + (wm * 2) * 4 * A_BLK_F4 + lane;
        const float2* bb = Bf + (buf * 2 + s) * B_SUB_F2 +
                           (lane & 3) * B_BLK_F2 + wn * 32 + (lane >> 2);
#pragma unroll
        for (int ks = 0; ks < 4; ++ks) {
            float4 a0 = ab[ks * A_BLK_F4];
            float4 a1 = ab[(4 + ks) * A_BLK_F4];
            const float2* bk = bb + ks * 4 * B_BLK_F2;
#pragma unroll
            for (int j = 0; j < 4; ++j) {
                float2 b = bk[j * 8];
                mma_tf32(acc[0][j],
                         __float_as_uint(a0.x), __float_as_uint(a0.y),
                         __float_as_uint(a0.z), __float_as_uint(a0.w),
                         __float_as_uint(b.x), __float_as_uint(b.y));
                mma_tf32(acc[1][j],
                         __float_as_uint(a1.x), __float_as_uint(a1.y),
                         __float_as_uint(a1.z), __float_as_uint(a1.w),
                         __float_as_uint(b.x), __float_as_uint(b.y));
            }
        }
    };

    // prologue: fill buffer 0 (both halves)
    ldg_half(0);  sts_half(0, 0);
    ldg_half(32); sts_half(0, 1);
    __syncthreads();

    for (int t = 0; t < NT; ++t) {
        const int cur = t & 1;
        const int nt = t + 1;
        const int nxt = nt & 1;

        if (nt < NT) ldg_half(nt * BK);          // prefetch half 0 of next tile
        compute_sub(cur, 0);
        if (nt < NT) { sts_half(nxt, 0); ldg_half(nt * BK + 32); }
        compute_sub(cur, 1);
        if (nt < NT) sts_half(nxt, 1);
        __syncthreads();
    }

    // ---- per-row lin/t reduce (A loaders only) ----
    if (isA) {
        linLo += __shfl_xor_sync(0xffffffffu, linLo, 1);
        linLo += __shfl_xor_sync(0xffffffffu, linLo, 2);
        linHi += __shfl_xor_sync(0xffffffffu, linHi, 1);
        linHi += __shfl_xor_sync(0xffffffffu, linHi, 2);
        tLo += __shfl_xor_sync(0xffffffffu, tLo, 1);
        tLo += __shfl_xor_sync(0xffffffffu, tLo, 2);
        tHi += __shfl_xor_sync(0xffffffffu, tHi, 1);
        tHi += __shfl_xor_sync(0xffffffffu, tHi, 2);
        if (cseg == 0) {
            rowLin[rlow] = linLo;  rowT[rlow] = tLo;
            rowLin[rlow + 8] = linHi;  rowT[rlow + 8] = tHi;
        }
    }

    // ---- epilogue: per-warp sum of squares over its 32 cols ----
#pragma unroll
    for (int i = 0; i < 2; ++i) {
        float sLo = 0.f, sHi = 0.f;
#pragma unroll
        for (int j = 0; j < 4; ++j) {
            sLo += acc[i][j][0] * acc[i][j][0] + acc[i][j][1] * acc[i][j][1];
            sHi += acc[i][j][2] * acc[i][j][2] + acc[i][j][3] * acc[i][j][3];
        }
        sLo += __shfl_xor_sync(0xffffffffu, sLo, 1);
        sLo += __shfl_xor_sync(0xffffffffu, sLo, 2);
        sHi += __shfl_xor_sync(0xffffffffu, sHi, 1);
        sHi += __shfl_xor_sync(0xffffffffu, sHi, 2);
        if ((lane & 3) == 0) {
            int rowL = wm * 32 + i * 16 + (lane >> 2);
            pS[rowL * 4 + wn] = sLo;
            pS[(rowL + 8) * 4 + wn] = sHi;
        }
    }
    __syncthreads();

    if (tid < BM) {
        float ssum = pS[tid * 4] + pS[tid * 4 + 1] + pS[tid * 4 + 2] + pS[tid * 4 + 3];
        float cross = 0.5f * (ssum - rowT[tid]) * (1.0f / (float)K_DIM);
        float z = rowLin[tid] + blin[0] + cross;
        out[blockRow + tid] = 1.0f / (1.0f + expf(-z));
    }
}

extern "C" void kernel_launch(void* const* d_in, const int* in_sizes, int n_in,
                              void* d_out, int out_size) {
    const float* x    = (const float*)d_in[0];
    const float* kern = (const float*)d_in[1];
    const float* wlin = (const float*)d_in[2];
    const float* blin = (const float*)d_in[3];
    float* out = (float*)d_out;
    const int B = out_size;

    cudaFuncSetAttribute(fm_mma_kernel,
                         cudaFuncAttributeMaxDynamicSharedMemorySize, SMEM_BYTES);
    prep_kernel<<<64, 256>>>(kern, wlin);
    fm_mma_kernel<<<B / BM, 512, SMEM_BYTES>>>(x, blin, out);
}